// round 9
// baseline (speedup 1.0000x reference)
#include <cuda_runtime.h>
#include <math.h>

// Problem constants (fixed by setup_inputs)
#define Bc 128          // batch
#define Nc 96           // num deltas
#define Dc 3072         // C*H*W
#define Kc 10           // classes
#define RPW 4           // rows (n-values) per warp-unit, same b
#define WARPS 16
#define THREADS (WARPS*32)               // 512
#define NUNITS (Bc * (Nc / RPW))         // 3072 units
#define GRID1 96                         // 96 CTAs * 16 warps = 1536 warps, 2 units each
#define WSLOTS (GRID1 * WARPS)           // 1536
#define SMEM_BYTES (Kc * Dc * 4)         // 122880 B

typedef unsigned long long u64;

__device__ float g_l1[Bc * Nc];
__device__ float g_l2[Bc * Nc];
__device__ float g_part[Bc];

// ---- packed f32x2 FMA (Blackwell; only add/sub/mul/fma exist, no sat/minmax) ----
#define FMA2(d, a, b, c) \
    asm("fma.rn.f32x2 %0, %1, %2, %3;" : "=l"(d) : "l"(a), "l"(b), "l"(c))

// ---- scalar saturating add: clip(a+b, 0, 1) in ONE instruction (FADD.SAT) ----
#define ADDSAT(d, a, b) \
    asm("add.rn.sat.f32 %0, %1, %2;" : "=f"(d) : "f"(a), "f"(b))

__device__ __forceinline__ u64 pack2(float lo, float hi) {
    u64 r;
    asm("mov.b64 %0, {%1, %2};" : "=l"(r) : "f"(lo), "f"(hi));
    return r;
}
__device__ __forceinline__ void unpack2(float& lo, float& hi, u64 v) {
    asm("mov.b64 {%0, %1}, %2;" : "=f"(lo), "=f"(hi) : "l"(v));
}

__global__ __launch_bounds__(THREADS, 1)
void logits_kernel(const float* __restrict__ imgs,
                   const float* __restrict__ deltas,
                   const float* __restrict__ Wm,
                   const float* __restrict__ bias,
                   const int*   __restrict__ labels)
{
    extern __shared__ float sW[];   // [Kc][Dc], transposed from W[d][k]

    // Cooperative load+transpose of W (coalesced global reads), once per CTA
    for (int idx = threadIdx.x; idx < Dc * Kc; idx += THREADS) {
        int d = idx / Kc, k = idx % Kc;
        sW[k * Dc + d] = Wm[idx];
    }
    __syncthreads();

    const int warp  = threadIdx.x >> 5;
    const int lane  = threadIdx.x & 31;
    const int wslot = blockIdx.x * WARPS + warp;   // 0..1535

    // exactly 2 units per warp: u and u+1536 (same b, so img row is L1-warm)
    for (int u = wslot; u < NUNITS; u += WSLOTS) {
        const int b  = u & (Bc - 1);
        const int n0 = (u >> 7) * RPW;

        const float4* img4 = (const float4*)(imgs + (size_t)b * Dc);
        const float4* dp0 = (const float4*)(deltas + ((size_t)(n0 + 0) * Bc + b) * Dc);
        const float4* dp1 = (const float4*)(deltas + ((size_t)(n0 + 1) * Bc + b) * Dc);
        const float4* dp2 = (const float4*)(deltas + ((size_t)(n0 + 2) * Bc + b) * Dc);
        const float4* dp3 = (const float4*)(deltas + ((size_t)(n0 + 3) * Bc + b) * Dc);

        u64 acc[RPW][Kc];
#pragma unroll
        for (int r = 0; r < RPW; r++)
#pragma unroll
            for (int k = 0; k < Kc; k++) acc[r][k] = 0ULL;

#pragma unroll 2
        for (int i = 0; i < Dc / 128; i++) {
            const int e = i * 32 + lane;            // float4 index within row
            float4 xi = __ldg(img4 + e);
            float4 dd0 = __ldcs(dp0 + e);
            float4 dd1 = __ldcs(dp1 + e);
            float4 dd2 = __ldcs(dp2 + e);
            float4 dd3 = __ldcs(dp3 + e);

            u64 xp[RPW][2];
            {
                float a0, a1, a2, a3;
                ADDSAT(a0, xi.x, dd0.x); ADDSAT(a1, xi.y, dd0.y);
                ADDSAT(a2, xi.z, dd0.z); ADDSAT(a3, xi.w, dd0.w);
                xp[0][0] = pack2(a0, a1); xp[0][1] = pack2(a2, a3);
            }
            {
                float a0, a1, a2, a3;
                ADDSAT(a0, xi.x, dd1.x); ADDSAT(a1, xi.y, dd1.y);
                ADDSAT(a2, xi.z, dd1.z); ADDSAT(a3, xi.w, dd1.w);
                xp[1][0] = pack2(a0, a1); xp[1][1] = pack2(a2, a3);
            }
            {
                float a0, a1, a2, a3;
                ADDSAT(a0, xi.x, dd2.x); ADDSAT(a1, xi.y, dd2.y);
                ADDSAT(a2, xi.z, dd2.z); ADDSAT(a3, xi.w, dd2.w);
                xp[2][0] = pack2(a0, a1); xp[2][1] = pack2(a2, a3);
            }
            {
                float a0, a1, a2, a3;
                ADDSAT(a0, xi.x, dd3.x); ADDSAT(a1, xi.y, dd3.y);
                ADDSAT(a2, xi.z, dd3.z); ADDSAT(a3, xi.w, dd3.w);
                xp[3][0] = pack2(a0, a1); xp[3][1] = pack2(a2, a3);
            }

#pragma unroll
            for (int k = 0; k < Kc; k++) {
                ulonglong2 w2 = *((const ulonglong2*)(sW + (size_t)k * Dc) + e);
#pragma unroll
                for (int r = 0; r < RPW; r++) {
                    FMA2(acc[r][k], xp[r][0], w2.x, acc[r][k]);
                    FMA2(acc[r][k], xp[r][1], w2.y, acc[r][k]);
                }
            }
        }

        // Per-row epilogue: warp reduce 10 logits, compute loss1/loss2
#pragma unroll
        for (int r = 0; r < RPW; r++) {
            float lg[Kc];
#pragma unroll
            for (int k = 0; k < Kc; k++) {
                float lo, hi;
                unpack2(lo, hi, acc[r][k]);
                float v = lo + hi;
                v += __shfl_xor_sync(0xFFFFFFFFu, v, 16);
                v += __shfl_xor_sync(0xFFFFFFFFu, v, 8);
                v += __shfl_xor_sync(0xFFFFFFFFu, v, 4);
                v += __shfl_xor_sync(0xFFFFFFFFu, v, 2);
                v += __shfl_xor_sync(0xFFFFFFFFu, v, 1);
                lg[k] = v;
            }
            if (lane == 0) {
#pragma unroll
                for (int k = 0; k < Kc; k++) lg[k] += __ldg(bias + k);

                // argmax (first occurrence, matches top_k tie rule)
                float m = lg[0]; int t1 = 0;
#pragma unroll
                for (int k = 1; k < Kc; k++)
                    if (lg[k] > m) { m = lg[k]; t1 = k; }

                float s = 0.0f;
#pragma unroll
                for (int k = 0; k < Kc; k++) s += expf(lg[k] - m);
                float lse = m + logf(s);

                int lab = __ldg(labels + b);
                float logit_lab = lg[0];
#pragma unroll
                for (int k = 1; k < Kc; k++)
                    if (k == lab) logit_lab = lg[k];
                float loss1 = lse - logit_lab;

                // second-best (first occurrence among k != t1)
                float m2 = -INFINITY; int t2 = 0;
#pragma unroll
                for (int k = 0; k < Kc; k++)
                    if (k != t1 && lg[k] > m2) { m2 = lg[k]; t2 = k; }
                float logit_t2 = lg[0];
#pragma unroll
                for (int k = 1; k < Kc; k++)
                    if (k == t2) logit_t2 = lg[k];

                float loss2 = (t1 == lab) ? (lse - logit_t2) : -10000.0f;

                g_l1[b * Nc + (n0 + r)] = loss1;
                g_l2[b * Nc + (n0 + r)] = loss2;
            }
        }
    }
}

// Per-batch-row stable rank-select (replicates stable argsort exactly)
__global__ void select_kernel(const int* __restrict__ indp)
{
    __shared__ float sd[Nc];
    __shared__ float sl1[Nc];
    __shared__ float sSel;

    const int b = blockIdx.x;
    const int j = threadIdx.x;   // 0..95

    float l1v = 0.0f, l2v = 0.0f, dv = 0.0f;
    if (j < Nc) {
        l1v = g_l1[b * Nc + j];
        l2v = g_l2[b * Nc + j];
        dv  = l1v - l2v;
        sd[j]  = dv;
        sl1[j] = l1v;
    }
    __syncthreads();

    const int ind = __ldg(indp);
    if (j < Nc) {
        int cnt = 0;
        for (int i = 0; i < Nc; i++) {
            float di = sd[i];
            cnt += (di < dv) || (di == dv && i < j);
        }
        if (cnt == ind) sSel = l2v;   // exactly one j satisfies this
    }
    __syncthreads();

    if (j == 0) {
        float s = 0.0f;
        for (int i = 0; i < Nc; i++) s += sl1[i];
        g_part[b] = s / (float)Nc - sSel;
    }
}

__global__ void reduce_kernel(float* __restrict__ out)
{
    if (threadIdx.x == 0) {
        float a = 0.0f;
#pragma unroll
        for (int i = 0; i < Bc; i++) a += g_part[i];
        out[0] = a / (float)Bc;
    }
}

extern "C" void kernel_launch(void* const* d_in, const int* in_sizes, int n_in,
                              void* d_out, int out_size)
{
    const float* imgs   = (const float*)d_in[0];
    const float* deltas = (const float*)d_in[1];
    const float* Wm     = (const float*)d_in[2];
    const float* bias   = (const float*)d_in[3];
    const int*   labels = (const int*)d_in[4];
    const int*   indp   = (const int*)d_in[5];
    float* out = (float*)d_out;

    cudaFuncSetAttribute(logits_kernel,
                         cudaFuncAttributeMaxDynamicSharedMemorySize, SMEM_BYTES);

    logits_kernel<<<GRID1, THREADS, SMEM_BYTES>>>(imgs, deltas, Wm, bias, labels);
    select_kernel<<<Bc, Nc>>>(indp);
    reduce_kernel<<<1, 32>>>(out);
}

// round 10
// speedup vs baseline: 1.0893x; 1.0893x over previous
#include <cuda_runtime.h>
#include <math.h>

// Problem constants (fixed by setup_inputs)
#define Bc 128          // batch
#define Nc 96           // num deltas
#define Dc 3072         // C*H*W
#define Kc 10           // classes
#define RPW 4           // rows (n-values) per warp-unit, same b
#define WARPS 16
#define THREADS (WARPS*32)               // 512
#define NUNITS (Bc * (Nc / RPW))         // 3072 units
#define GRID1 96                         // 96 CTAs * 16 warps = 1536 warps, 2 units each
#define WSLOTS (GRID1 * WARPS)           // 1536
#define SMEM_BYTES (Kc * Dc * 4 + 64)    // W transpose + bias

typedef unsigned long long u64;

__device__ float g_l1[Bc * Nc];
__device__ float g_l2[Bc * Nc];
__device__ float g_part[Bc];

// ---- packed f32x2 FMA (Blackwell; only add/sub/mul/fma exist in f32x2) ----
#define FMA2(d, a, b, c) \
    asm("fma.rn.f32x2 %0, %1, %2, %3;" : "=l"(d) : "l"(a), "l"(b), "l"(c))

// ---- scalar saturating add: clip(a+b, 0, 1) in ONE instruction (FADD.SAT) ----
#define ADDSAT(d, a, b) \
    asm("add.rn.sat.f32 %0, %1, %2;" : "=f"(d) : "f"(a), "f"(b))

__device__ __forceinline__ u64 pack2(float lo, float hi) {
    u64 r;
    asm("mov.b64 %0, {%1, %2};" : "=l"(r) : "f"(lo), "f"(hi));
    return r;
}
__device__ __forceinline__ void unpack2(float& lo, float& hi, u64 v) {
    asm("mov.b64 {%0, %1}, %2;" : "=f"(lo), "=f"(hi) : "l"(v));
}

__global__ __launch_bounds__(THREADS, 1)
void logits_kernel(const float* __restrict__ imgs,
                   const float* __restrict__ deltas,
                   const float* __restrict__ Wm,
                   const float* __restrict__ bias,
                   const int*   __restrict__ labels)
{
    extern __shared__ float sW[];        // [Kc][Dc] transposed W, then bias[16]
    float* sBias = sW + Kc * Dc;

    // Cooperative load+transpose of W (coalesced global reads), once per CTA
    for (int idx = threadIdx.x; idx < Dc * Kc; idx += THREADS) {
        int d = idx / Kc, k = idx % Kc;
        sW[k * Dc + d] = Wm[idx];
    }
    if (threadIdx.x < Kc) sBias[threadIdx.x] = bias[threadIdx.x];
    __syncthreads();

    const int warp  = threadIdx.x >> 5;
    const int lane  = threadIdx.x & 31;
    const int wslot = blockIdx.x * WARPS + warp;   // 0..1535

    // exactly 2 units per warp: u and u+1536 (same b, so img row is L1-warm)
    for (int u = wslot; u < NUNITS; u += WSLOTS) {
        const int b  = u & (Bc - 1);
        const int n0 = (u >> 7) * RPW;

        const float4* img4 = (const float4*)(imgs + (size_t)b * Dc) + lane;
        const float4* dp0 = (const float4*)(deltas + ((size_t)(n0 + 0) * Bc + b) * Dc) + lane;
        const float4* dp1 = (const float4*)(deltas + ((size_t)(n0 + 1) * Bc + b) * Dc) + lane;
        const float4* dp2 = (const float4*)(deltas + ((size_t)(n0 + 2) * Bc + b) * Dc) + lane;
        const float4* dp3 = (const float4*)(deltas + ((size_t)(n0 + 3) * Bc + b) * Dc) + lane;
        const ulonglong2* w0 = (const ulonglong2*)sW + lane;

        u64 acc[RPW][Kc];
#pragma unroll
        for (int r = 0; r < RPW; r++)
#pragma unroll
            for (int k = 0; k < Kc; k++) acc[r][k] = 0ULL;

#pragma unroll 1
        for (int i = 0; i < Dc / 128; i++) {
            const int e = i * 32;                   // float4 offset within row
            float4 xi  = __ldg(img4 + e);
            float4 dd0 = __ldcs(dp0 + e);
            float4 dd1 = __ldcs(dp1 + e);
            float4 dd2 = __ldcs(dp2 + e);
            float4 dd3 = __ldcs(dp3 + e);

            u64 xp[RPW][2];
            {
                float a0, a1, a2, a3;
                ADDSAT(a0, xi.x, dd0.x); ADDSAT(a1, xi.y, dd0.y);
                ADDSAT(a2, xi.z, dd0.z); ADDSAT(a3, xi.w, dd0.w);
                xp[0][0] = pack2(a0, a1); xp[0][1] = pack2(a2, a3);
            }
            {
                float a0, a1, a2, a3;
                ADDSAT(a0, xi.x, dd1.x); ADDSAT(a1, xi.y, dd1.y);
                ADDSAT(a2, xi.z, dd1.z); ADDSAT(a3, xi.w, dd1.w);
                xp[1][0] = pack2(a0, a1); xp[1][1] = pack2(a2, a3);
            }
            {
                float a0, a1, a2, a3;
                ADDSAT(a0, xi.x, dd2.x); ADDSAT(a1, xi.y, dd2.y);
                ADDSAT(a2, xi.z, dd2.z); ADDSAT(a3, xi.w, dd2.w);
                xp[2][0] = pack2(a0, a1); xp[2][1] = pack2(a2, a3);
            }
            {
                float a0, a1, a2, a3;
                ADDSAT(a0, xi.x, dd3.x); ADDSAT(a1, xi.y, dd3.y);
                ADDSAT(a2, xi.z, dd3.z); ADDSAT(a3, xi.w, dd3.w);
                xp[3][0] = pack2(a0, a1); xp[3][1] = pack2(a2, a3);
            }

#pragma unroll
            for (int k = 0; k < Kc; k++) {
                ulonglong2 w2 = w0[k * (Dc / 4) + e];
                FMA2(acc[0][k], xp[0][0], w2.x, acc[0][k]);
                FMA2(acc[0][k], xp[0][1], w2.y, acc[0][k]);
                FMA2(acc[1][k], xp[1][0], w2.x, acc[1][k]);
                FMA2(acc[1][k], xp[1][1], w2.y, acc[1][k]);
                FMA2(acc[2][k], xp[2][0], w2.x, acc[2][k]);
                FMA2(acc[2][k], xp[2][1], w2.y, acc[2][k]);
                FMA2(acc[3][k], xp[3][0], w2.x, acc[3][k]);
                FMA2(acc[3][k], xp[3][1], w2.y, acc[3][k]);
            }
        }

        // Per-row epilogue: warp reduce 10 logits, compute loss1/loss2
#pragma unroll
        for (int r = 0; r < RPW; r++) {
            float lg[Kc];
#pragma unroll
            for (int k = 0; k < Kc; k++) {
                float lo, hi;
                unpack2(lo, hi, acc[r][k]);
                float v = lo + hi;
                v += __shfl_xor_sync(0xFFFFFFFFu, v, 16);
                v += __shfl_xor_sync(0xFFFFFFFFu, v, 8);
                v += __shfl_xor_sync(0xFFFFFFFFu, v, 4);
                v += __shfl_xor_sync(0xFFFFFFFFu, v, 2);
                v += __shfl_xor_sync(0xFFFFFFFFu, v, 1);
                lg[k] = v;
            }
            if (lane == 0) {
#pragma unroll
                for (int k = 0; k < Kc; k++) lg[k] += sBias[k];

                // argmax (first occurrence, matches top_k tie rule)
                float m = lg[0]; int t1 = 0;
#pragma unroll
                for (int k = 1; k < Kc; k++)
                    if (lg[k] > m) { m = lg[k]; t1 = k; }

                float s = 0.0f;
#pragma unroll
                for (int k = 0; k < Kc; k++) s += expf(lg[k] - m);
                float lse = m + logf(s);

                int lab = __ldg(labels + b);
                float logit_lab = lg[0];
#pragma unroll
                for (int k = 1; k < Kc; k++)
                    if (k == lab) logit_lab = lg[k];
                float loss1 = lse - logit_lab;

                // second-best (first occurrence among k != t1)
                float m2 = -INFINITY; int t2 = 0;
#pragma unroll
                for (int k = 0; k < Kc; k++)
                    if (k != t1 && lg[k] > m2) { m2 = lg[k]; t2 = k; }
                float logit_t2 = lg[0];
#pragma unroll
                for (int k = 1; k < Kc; k++)
                    if (k == t2) logit_t2 = lg[k];

                float loss2 = (t1 == lab) ? (lse - logit_t2) : -10000.0f;

                g_l1[b * Nc + (n0 + r)] = loss1;
                g_l2[b * Nc + (n0 + r)] = loss2;
            }
        }
    }
}

// Per-batch-row stable rank-select (replicates stable argsort exactly)
__global__ void select_kernel(const int* __restrict__ indp)
{
    __shared__ float sd[Nc];
    __shared__ float sl1[Nc];
    __shared__ float sSel;

    const int b = blockIdx.x;
    const int j = threadIdx.x;   // 0..95

    float l1v = 0.0f, l2v = 0.0f, dv = 0.0f;
    if (j < Nc) {
        l1v = g_l1[b * Nc + j];
        l2v = g_l2[b * Nc + j];
        dv  = l1v - l2v;
        sd[j]  = dv;
        sl1[j] = l1v;
    }
    __syncthreads();

    const int ind = __ldg(indp);
    if (j < Nc) {
        int cnt = 0;
        for (int i = 0; i < Nc; i++) {
            float di = sd[i];
            cnt += (di < dv) || (di == dv && i < j);
        }
        if (cnt == ind) sSel = l2v;   // exactly one j satisfies this
    }
    __syncthreads();

    if (j == 0) {
        float s = 0.0f;
        for (int i = 0; i < Nc; i++) s += sl1[i];
        g_part[b] = s / (float)Nc - sSel;
    }
}

__global__ void reduce_kernel(float* __restrict__ out)
{
    if (threadIdx.x == 0) {
        float a = 0.0f;
#pragma unroll
        for (int i = 0; i < Bc; i++) a += g_part[i];
        out[0] = a / (float)Bc;
    }
}

extern "C" void kernel_launch(void* const* d_in, const int* in_sizes, int n_in,
                              void* d_out, int out_size)
{
    const float* imgs   = (const float*)d_in[0];
    const float* deltas = (const float*)d_in[1];
    const float* Wm     = (const float*)d_in[2];
    const float* bias   = (const float*)d_in[3];
    const int*   labels = (const int*)d_in[4];
    const int*   indp   = (const int*)d_in[5];
    float* out = (float*)d_out;

    cudaFuncSetAttribute(logits_kernel,
                         cudaFuncAttributeMaxDynamicSharedMemorySize, SMEM_BYTES);

    logits_kernel<<<GRID1, THREADS, SMEM_BYTES>>>(imgs, deltas, Wm, bias, labels);
    select_kernel<<<Bc, Nc>>>(indp);
    reduce_kernel<<<1, 32>>>(out);
}

// round 13
// speedup vs baseline: 1.3496x; 1.2389x over previous
#include <cuda_runtime.h>
#include <math.h>

// Problem constants (fixed by setup_inputs)
#define Bc 128          // batch
#define Nc 96           // num deltas
#define Dc 3072         // C*H*W
#define Kc 10           // classes
#define RPW 2           // rows (n-values) per warp-unit, same b
#define WARPS 24
#define THREADS (WARPS*32)               // 768
#define NUNITS (Bc * (Nc / RPW))         // 6144 units
#define GRID1 128                        // 128 CTAs * 24 warps = 3072 warps, 2 units each
#define WSLOTS (GRID1 * WARPS)           // 3072
#define SMEM_BYTES (Kc * Dc * 4 + 64)    // W transpose + bias

typedef unsigned long long u64;

__device__ float g_l1[Bc * Nc];
__device__ float g_l2[Bc * Nc];
__device__ float g_part[Bc];

// ---- packed f32x2 FMA (Blackwell; only add/sub/mul/fma exist in f32x2) ----
#define FMA2(d, a, b, c) \
    asm("fma.rn.f32x2 %0, %1, %2, %3;" : "=l"(d) : "l"(a), "l"(b), "l"(c))

// ---- scalar saturating add: clip(a+b, 0, 1) in ONE instruction (FADD.SAT) ----
#define ADDSAT(d, a, b) \
    asm("add.rn.sat.f32 %0, %1, %2;" : "=f"(d) : "f"(a), "f"(b))

__device__ __forceinline__ u64 pack2(float lo, float hi) {
    u64 r;
    asm("mov.b64 %0, {%1, %2};" : "=l"(r) : "f"(lo), "f"(hi));
    return r;
}
__device__ __forceinline__ void unpack2(float& lo, float& hi, u64 v) {
    asm("mov.b64 {%0, %1}, %2;" : "=f"(lo), "=f"(hi) : "l"(v));
}

__global__ __launch_bounds__(THREADS, 1)
void logits_kernel(const float* __restrict__ imgs,
                   const float* __restrict__ deltas,
                   const float* __restrict__ Wm,
                   const float* __restrict__ bias,
                   const int*   __restrict__ labels)
{
    extern __shared__ float sW[];        // [Kc][Dc] transposed W, then bias[16]
    float* sBias = sW + Kc * Dc;

    // Cooperative load+transpose of W (coalesced global reads), once per CTA
    for (int idx = threadIdx.x; idx < Dc * Kc; idx += THREADS) {
        int d = idx / Kc, k = idx % Kc;
        sW[k * Dc + d] = Wm[idx];
    }
    if (threadIdx.x < Kc) sBias[threadIdx.x] = bias[threadIdx.x];
    __syncthreads();

    const int warp  = threadIdx.x >> 5;
    const int lane  = threadIdx.x & 31;
    const int wslot = blockIdx.x * WARPS + warp;   // 0..3071

    // exactly 2 units per warp: u and u+3072 (same b, so img row is L1-warm)
    for (int u = wslot; u < NUNITS; u += WSLOTS) {
        const int b  = u & (Bc - 1);
        const int n0 = (u >> 7) * RPW;

        const float4* img4 = (const float4*)(imgs + (size_t)b * Dc) + lane;
        const float4* dp0 = (const float4*)(deltas + ((size_t)(n0 + 0) * Bc + b) * Dc) + lane;
        const float4* dp1 = (const float4*)(deltas + ((size_t)(n0 + 1) * Bc + b) * Dc) + lane;
        const ulonglong2* w0 = (const ulonglong2*)sW + lane;

        u64 acc[RPW][Kc];
#pragma unroll
        for (int r = 0; r < RPW; r++)
#pragma unroll
            for (int k = 0; k < Kc; k++) acc[r][k] = 0ULL;

#pragma unroll 1
        for (int i = 0; i < Dc / 128; i++) {
            const int e = i * 32;                   // float4 offset within row
            float4 xi  = __ldg(img4 + e);
            float4 dd0 = __ldcs(dp0 + e);
            float4 dd1 = __ldcs(dp1 + e);

            u64 xp[RPW][2];
            {
                float a0, a1, a2, a3;
                ADDSAT(a0, xi.x, dd0.x); ADDSAT(a1, xi.y, dd0.y);
                ADDSAT(a2, xi.z, dd0.z); ADDSAT(a3, xi.w, dd0.w);
                xp[0][0] = pack2(a0, a1); xp[0][1] = pack2(a2, a3);
            }
            {
                float a0, a1, a2, a3;
                ADDSAT(a0, xi.x, dd1.x); ADDSAT(a1, xi.y, dd1.y);
                ADDSAT(a2, xi.z, dd1.z); ADDSAT(a3, xi.w, dd1.w);
                xp[1][0] = pack2(a0, a1); xp[1][1] = pack2(a2, a3);
            }

#pragma unroll
            for (int k = 0; k < Kc; k++) {
                ulonglong2 w2 = w0[k * (Dc / 4) + e];
                FMA2(acc[0][k], xp[0][0], w2.x, acc[0][k]);
                FMA2(acc[0][k], xp[0][1], w2.y, acc[0][k]);
                FMA2(acc[1][k], xp[1][0], w2.x, acc[1][k]);
                FMA2(acc[1][k], xp[1][1], w2.y, acc[1][k]);
            }
        }

        // Per-row epilogue: warp reduce 10 logits, compute loss1/loss2
#pragma unroll
        for (int r = 0; r < RPW; r++) {
            float lg[Kc];
#pragma unroll
            for (int k = 0; k < Kc; k++) {
                float lo, hi;
                unpack2(lo, hi, acc[r][k]);
                float v = lo + hi;
                v += __shfl_xor_sync(0xFFFFFFFFu, v, 16);
                v += __shfl_xor_sync(0xFFFFFFFFu, v, 8);
                v += __shfl_xor_sync(0xFFFFFFFFu, v, 4);
                v += __shfl_xor_sync(0xFFFFFFFFu, v, 2);
                v += __shfl_xor_sync(0xFFFFFFFFu, v, 1);
                lg[k] = v;
            }
            if (lane == 0) {
#pragma unroll
                for (int k = 0; k < Kc; k++) lg[k] += sBias[k];

                // argmax (first occurrence, matches top_k tie rule)
                float m = lg[0]; int t1 = 0;
#pragma unroll
                for (int k = 1; k < Kc; k++)
                    if (lg[k] > m) { m = lg[k]; t1 = k; }

                float s = 0.0f;
#pragma unroll
                for (int k = 0; k < Kc; k++) s += expf(lg[k] - m);
                float lse = m + logf(s);

                int lab = __ldg(labels + b);
                float logit_lab = lg[0];
#pragma unroll
                for (int k = 1; k < Kc; k++)
                    if (k == lab) logit_lab = lg[k];
                float loss1 = lse - logit_lab;

                // second-best (first occurrence among k != t1)
                float m2 = -INFINITY; int t2 = 0;
#pragma unroll
                for (int k = 0; k < Kc; k++)
                    if (k != t1 && lg[k] > m2) { m2 = lg[k]; t2 = k; }
                float logit_t2 = lg[0];
#pragma unroll
                for (int k = 1; k < Kc; k++)
                    if (k == t2) logit_t2 = lg[k];

                float loss2 = (t1 == lab) ? (lse - logit_t2) : -10000.0f;

                g_l1[b * Nc + (n0 + r)] = loss1;
                g_l2[b * Nc + (n0 + r)] = loss2;
            }
        }
    }
}

// Per-batch-row stable rank-select (replicates stable argsort exactly)
__global__ void select_kernel(const int* __restrict__ indp)
{
    __shared__ float sd[Nc];
    __shared__ float sl1[Nc];
    __shared__ float sSel;

    const int b = blockIdx.x;
    const int j = threadIdx.x;   // 0..95

    float l1v = 0.0f, l2v = 0.0f, dv = 0.0f;
    if (j < Nc) {
        l1v = g_l1[b * Nc + j];
        l2v = g_l2[b * Nc + j];
        dv  = l1v - l2v;
        sd[j]  = dv;
        sl1[j] = l1v;
    }
    __syncthreads();

    const int ind = __ldg(indp);
    if (j < Nc) {
        int cnt = 0;
        for (int i = 0; i < Nc; i++) {
            float di = sd[i];
            cnt += (di < dv) || (di == dv && i < j);
        }
        if (cnt == ind) sSel = l2v;   // exactly one j satisfies this
    }
    __syncthreads();

    if (j == 0) {
        float s = 0.0f;
        for (int i = 0; i < Nc; i++) s += sl1[i];
        g_part[b] = s / (float)Nc - sSel;
    }
}

__global__ void reduce_kernel(float* __restrict__ out)
{
    if (threadIdx.x == 0) {
        float a = 0.0f;
#pragma unroll
        for (int i = 0; i < Bc; i++) a += g_part[i];
        out[0] = a / (float)Bc;
    }
}

extern "C" void kernel_launch(void* const* d_in, const int* in_sizes, int n_in,
                              void* d_out, int out_size)
{
    const float* imgs   = (const float*)d_in[0];
    const float* deltas = (const float*)d_in[1];
    const float* Wm     = (const float*)d_in[2];
    const float* bias   = (const float*)d_in[3];
    const int*   labels = (const int*)d_in[4];
    const int*   indp   = (const int*)d_in[5];
    float* out = (float*)d_out;

    cudaFuncSetAttribute(logits_kernel,
                         cudaFuncAttributeMaxDynamicSharedMemorySize, SMEM_BYTES);

    logits_kernel<<<GRID1, THREADS, SMEM_BYTES>>>(imgs, deltas, Wm, bias, labels);
    select_kernel<<<Bc, Nc>>>(indp);
    reduce_kernel<<<1, 32>>>(out);
}